// round 9
// baseline (speedup 1.0000x reference)
#include <cuda_runtime.h>
#include <cuda_fp16.h>

// CapsuleLayer dynamic routing — BT=2, full-line W loads, fp16 pair-packed
// P/E (fp32 compute), 2 CTAs/SM.
// x: [256, 1152, 8] f32 ; W: [10, 1152, 8, 16] f32 ; out: [256, 10, 16] f32
#define NB 256
#define NC 10
#define NR 1152
#define IC 8
#define OC 16
#define THREADS 1024
#define BT 2
#define PSTR2 1154                // Pp row stride in half2 units (≡2 mod 32)
#define P2_UNITS (OC * PSTR2)     // 18464 4-byte units
#define NUM_ITER 3

// SMEM 4B units: Pp | Ep[1156] | red2[32*33] | S2[64] | V[32] | red[64] | aux[8]
#define SMEM_FLOATS (P2_UNITS + 1156 + 32 * 33 + 64 + 32 + 64 + 8)

extern "C" __global__ void __launch_bounds__(THREADS, 2)
caps_route_kernel(const float* __restrict__ x,
                  const float* __restrict__ W,
                  float* __restrict__ out)
{
    extern __shared__ float sm[];
    __half2* Pp   = reinterpret_cast<__half2*>(sm);        // [oc][r], x=b0 y=b1
    __half2* Ep   = reinterpret_cast<__half2*>(sm + P2_UNITS);
    float*   red2 = sm + P2_UNITS + 1156;                  // [32][33]
    float*   S2   = red2 + 32 * 33;                        // [rhalf][b*16+oc]
    float*   V    = S2 + 64;                               // 16B aligned
    float*   red  = V + 32;
    float*   aux  = red + 64;

    const int tid  = threadIdx.x;
    const int lane = tid & 31;
    const int wid  = tid >> 5;

    const int b0 = blockIdx.x * BT;
    const int c  = blockIdx.y;

    const float*  xb0 = x + (size_t)b0 * NR * IC;
    const float*  xb1 = xb0 + NR * IC;
    const float4* Wc4 = reinterpret_cast<const float4*>(
                            W + (size_t)c * NR * IC * OC);

    // ============ Phase 1: priors — full-line W loads, 1-level shfl merge ====
    // lane = rloc*8 + q ; q = qi*4 + sub. Warp-instr k loads 4 rows' full
    // 128B line (i-pair k). Post-merge BOTH qi twins hold complete aA/aB;
    // qi=0 stores oc ob+0,ob+1, qi=1 stores ob+2,ob+3 as half2(b0,b1).
    {
        const int rloc  = lane >> 3;
        const int q     = lane & 7;
        const int qi    = q >> 2;
        const int sub   = q & 3;
        const int rbase = wid * 4 + rloc;

        float sA0 = 0.f, sA1 = 0.f, sA2 = 0.f, sA3 = 0.f;
        float sB0 = 0.f, sB1 = 0.f, sB2 = 0.f, sB3 = 0.f;

        #pragma unroll 3
        for (int it = 0; it < 9; ++it) {
            const int r = rbase + it * 128;
            const float4* wp = Wc4 + (size_t)r * 32 + q;
            const float4 w0 = wp[0];
            const float4 w1 = wp[8];
            const float4 w2 = wp[16];
            const float4 w3 = wp[24];
            const float4 xa0 = reinterpret_cast<const float4*>(xb0 + r * IC)[0];
            const float4 xa1 = reinterpret_cast<const float4*>(xb0 + r * IC)[1];
            const float4 xc0 = reinterpret_cast<const float4*>(xb1 + r * IC)[0];
            const float4 xc1 = reinterpret_cast<const float4*>(xb1 + r * IC)[1];

            const float xA0 = qi ? xa0.y : xa0.x;
            const float xA1 = qi ? xa0.w : xa0.z;
            const float xA2 = qi ? xa1.y : xa1.x;
            const float xA3 = qi ? xa1.w : xa1.z;
            const float xB0 = qi ? xc0.y : xc0.x;
            const float xB1 = qi ? xc0.w : xc0.z;
            const float xB2 = qi ? xc1.y : xc1.x;
            const float xB3 = qi ? xc1.w : xc1.z;

            float aA0, aA1, aA2, aA3, aB0, aB1, aB2, aB3;
            aA0 = xA0 * w0.x; aA1 = xA0 * w0.y; aA2 = xA0 * w0.z; aA3 = xA0 * w0.w;
            aB0 = xB0 * w0.x; aB1 = xB0 * w0.y; aB2 = xB0 * w0.z; aB3 = xB0 * w0.w;
            aA0 = fmaf(xA1, w1.x, aA0); aA1 = fmaf(xA1, w1.y, aA1);
            aA2 = fmaf(xA1, w1.z, aA2); aA3 = fmaf(xA1, w1.w, aA3);
            aB0 = fmaf(xB1, w1.x, aB0); aB1 = fmaf(xB1, w1.y, aB1);
            aB2 = fmaf(xB1, w1.z, aB2); aB3 = fmaf(xB1, w1.w, aB3);
            aA0 = fmaf(xA2, w2.x, aA0); aA1 = fmaf(xA2, w2.y, aA1);
            aA2 = fmaf(xA2, w2.z, aA2); aA3 = fmaf(xA2, w2.w, aA3);
            aB0 = fmaf(xB2, w2.x, aB0); aB1 = fmaf(xB2, w2.y, aB1);
            aB2 = fmaf(xB2, w2.z, aB2); aB3 = fmaf(xB2, w2.w, aB3);
            aA0 = fmaf(xA3, w3.x, aA0); aA1 = fmaf(xA3, w3.y, aA1);
            aA2 = fmaf(xA3, w3.z, aA2); aA3 = fmaf(xA3, w3.w, aA3);
            aB0 = fmaf(xB3, w3.x, aB0); aB1 = fmaf(xB3, w3.y, aB1);
            aB2 = fmaf(xB3, w3.z, aB2); aB3 = fmaf(xB3, w3.w, aB3);

            // merge i-parities — both twins end with complete sums
            aA0 += __shfl_xor_sync(0xFFFFFFFFu, aA0, 4);
            aA1 += __shfl_xor_sync(0xFFFFFFFFu, aA1, 4);
            aA2 += __shfl_xor_sync(0xFFFFFFFFu, aA2, 4);
            aA3 += __shfl_xor_sync(0xFFFFFFFFu, aA3, 4);
            aB0 += __shfl_xor_sync(0xFFFFFFFFu, aB0, 4);
            aB1 += __shfl_xor_sync(0xFFFFFFFFu, aB1, 4);
            aB2 += __shfl_xor_sync(0xFFFFFFFFu, aB2, 4);
            aB3 += __shfl_xor_sync(0xFFFFFFFFu, aB3, 4);

            // twins split the 4 packed stores (banks all-distinct per instr)
            const int ob = sub * 4 + qi * 2;
            const float p0a = qi ? aA2 : aA0;
            const float p0b = qi ? aB2 : aB0;
            const float p1a = qi ? aA3 : aA1;
            const float p1b = qi ? aB3 : aB1;
            Pp[(ob + 0) * PSTR2 + r] = __floats2half2_rn(p0a, p0b);
            Pp[(ob + 1) * PSTR2 + r] = __floats2half2_rn(p1a, p1b);

            sA0 += aA0; sA1 += aA1; sA2 += aA2; sA3 += aA3;
            sB0 += aB0; sB1 += aB1; sB2 += aB2; sB3 += aB3;
        }

        // reduce iter0 sums over rloc (lane bits 3,4); twins duplicate
        #pragma unroll
        for (int off = 8; off <= 16; off <<= 1) {
            sA0 += __shfl_xor_sync(0xFFFFFFFFu, sA0, off);
            sA1 += __shfl_xor_sync(0xFFFFFFFFu, sA1, off);
            sA2 += __shfl_xor_sync(0xFFFFFFFFu, sA2, off);
            sA3 += __shfl_xor_sync(0xFFFFFFFFu, sA3, off);
            sB0 += __shfl_xor_sync(0xFFFFFFFFu, sB0, off);
            sB1 += __shfl_xor_sync(0xFFFFFFFFu, sB1, off);
            sB2 += __shfl_xor_sync(0xFFFFFFFFu, sB2, off);
            sB3 += __shfl_xor_sync(0xFFFFFFFFu, sB3, off);
        }
        if (lane < 4) {           // rloc=0, qi=0, sub=lane
            float* row = red2 + wid * 33;
            row[lane * 4 + 0] = sA0;  row[lane * 4 + 1] = sA1;
            row[lane * 4 + 2] = sA2;  row[lane * 4 + 3] = sA3;
            row[16 + lane * 4 + 0] = sB0;  row[16 + lane * 4 + 1] = sB1;
            row[16 + lane * 4 + 2] = sB2;  row[16 + lane * 4 + 3] = sB3;
        }
    }
    __syncthreads();

    // ============ iter 0: squash from fused fp32 sums ========================
    const float inv_nr = 1.0f / (float)NR;
    if (wid == 0) {
        float s = 0.f;
        #pragma unroll
        for (int w2 = 0; w2 < 32; ++w2) s += red2[w2 * 33 + lane];
        float sv = s * inv_nr;
        float sq = sv * sv;
        #pragma unroll
        for (int off = 8; off > 0; off >>= 1)
            sq += __shfl_xor_sync(0xFFFFFFFFu, sq, off);   // within 16-half
        const float sc = sq / ((1.f + sq) * sqrtf(sq));
        V[lane] = sv * sc;
    }
    __syncthreads();

    // ============ Phase 2: routing iterations 1..2 ===========================
    const int  ra   = tid;
    const int  rb   = tid + THREADS;
    const bool hasb = (tid < NR - THREADS);   // tid < 128

    float La0 = 0.f, La1 = 0.f;
    float Lb0 = 0.f, Lb1 = 0.f;

    // WS mapping: warp = (r-half, oc)
    const int wsoc = wid & 15;
    const int wsrh = wid >> 4;
    const int rst  = wsrh * (NR / 2);

    for (int iter = 1; iter < NUM_ITER; ++iter) {
        // ---- delta logits (reads V of previous iteration; half2 P) ----
        {
            const float4* V4 = reinterpret_cast<const float4*>(V);
            float da0 = 0.f, da1 = 0.f, db0 = 0.f, db1 = 0.f;
            #pragma unroll
            for (int o4 = 0; o4 < 4; ++o4) {
                const float4 v0 = V4[o4];
                const float4 v1 = V4[4 + o4];
                const float v0a[4] = {v0.x, v0.y, v0.z, v0.w};
                const float v1a[4] = {v1.x, v1.y, v1.z, v1.w};
                #pragma unroll
                for (int j = 0; j < 4; ++j) {
                    const int oc = o4 * 4 + j;
                    const float2 f = __half22float2(Pp[oc * PSTR2 + ra]);
                    da0 = fmaf(f.x, v0a[j], da0);
                    da1 = fmaf(f.y, v1a[j], da1);
                    if (hasb) {
                        const float2 g = __half22float2(Pp[oc * PSTR2 + rb]);
                        db0 = fmaf(g.x, v0a[j], db0);
                        db1 = fmaf(g.y, v1a[j], db1);
                    }
                }
            }
            La0 += da0; La1 += da1;
            Lb0 += db0; Lb1 += db1;
        }

        // ---- softmax over r (both batches, fp32) ----
        {
            float m0 = La0, m1 = La1;
            if (hasb) { m0 = fmaxf(m0, Lb0); m1 = fmaxf(m1, Lb1); }
            #pragma unroll
            for (int off = 16; off > 0; off >>= 1) {
                m0 = fmaxf(m0, __shfl_xor_sync(0xFFFFFFFFu, m0, off));
                m1 = fmaxf(m1, __shfl_xor_sync(0xFFFFFFFFu, m1, off));
            }
            if (lane == 0) { red[wid] = m0; red[32 + wid] = m1; }
            __syncthreads();
            if (wid < 2) {
                float v = red[wid * 32 + lane];
                #pragma unroll
                for (int off = 16; off > 0; off >>= 1)
                    v = fmaxf(v, __shfl_xor_sync(0xFFFFFFFFu, v, off));
                if (lane == 0) aux[wid] = v;
            }
            __syncthreads();
            m0 = aux[0]; m1 = aux[1];

            float s0, s1;
            {
                const float ea0 = __expf(La0 - m0);
                const float ea1 = __expf(La1 - m1);
                Ep[ra] = __floats2half2_rn(ea0, ea1);
                s0 = ea0; s1 = ea1;
                if (hasb) {
                    const float eb0 = __expf(Lb0 - m0);
                    const float eb1 = __expf(Lb1 - m1);
                    Ep[rb] = __floats2half2_rn(eb0, eb1);
                    s0 += eb0; s1 += eb1;
                }
            }
            #pragma unroll
            for (int off = 16; off > 0; off >>= 1) {
                s0 += __shfl_xor_sync(0xFFFFFFFFu, s0, off);
                s1 += __shfl_xor_sync(0xFFFFFFFFu, s1, off);
            }
            if (lane == 0) { red[wid] = s0; red[32 + wid] = s1; }
            __syncthreads();
            if (wid < 2) {
                float v = red[wid * 32 + lane];
                #pragma unroll
                for (int off = 16; off > 0; off >>= 1)
                    v += __shfl_xor_sync(0xFFFFFFFFu, v, off);
                if (lane == 0) aux[2 + wid] = 1.0f / v;
            }
            __syncthreads();   // Ep + aux visible
        }

        // ---- weighted sum: warp (r-half, oc); one half2 scan = both batches --
        {
            const __half2* pc = Pp + wsoc * PSTR2;
            float a0 = 0.f, a1 = 0.f;
            #pragma unroll 3
            for (int rr = rst + lane; rr < rst + NR / 2; rr += 32) {
                const float2 e = __half22float2(Ep[rr]);
                const float2 p = __half22float2(pc[rr]);
                a0 = fmaf(e.x, p.x, a0);
                a1 = fmaf(e.y, p.y, a1);
            }
            #pragma unroll
            for (int off = 16; off > 0; off >>= 1) {
                a0 += __shfl_xor_sync(0xFFFFFFFFu, a0, off);
                a1 += __shfl_xor_sync(0xFFFFFFFFu, a1, off);
            }
            if (lane == 0) {
                S2[wsrh * 32 + wsoc]      = a0;   // batch 0
                S2[wsrh * 32 + 16 + wsoc] = a1;   // batch 1
            }
        }
        __syncthreads();

        // ---- squash (warp 0; lanes 0-15 b0, 16-31 b1) ----
        if (wid == 0) {
            float sv = (S2[lane] + S2[32 + lane]) * aux[2 + (lane >> 4)];
            float sq = sv * sv;
            #pragma unroll
            for (int off = 8; off > 0; off >>= 1)
                sq += __shfl_xor_sync(0xFFFFFFFFu, sq, off);
            const float sc = sq / ((1.f + sq) * sqrtf(sq));
            V[lane] = sv * sc;
        }
        __syncthreads();
    }

    // ============ Phase 3: output ============================================
    if (tid < 2 * OC) {
        const int obb = tid >> 4;
        out[((size_t)(b0 + obb) * NC + c) * OC + (tid & 15)] = V[tid];
    }
}

extern "C" void kernel_launch(void* const* d_in, const int* in_sizes, int n_in,
                              void* d_out, int out_size)
{
    (void)in_sizes; (void)n_in; (void)out_size;
    const float* x = (const float*)d_in[0];
    const float* W = (const float*)d_in[1];
    float* out = (float*)d_out;

    static int smem_set = 0;
    const int smem_bytes = SMEM_FLOATS * sizeof(float);
    if (!smem_set) {
        cudaFuncSetAttribute(caps_route_kernel,
                             cudaFuncAttributeMaxDynamicSharedMemorySize,
                             smem_bytes);
        smem_set = 1;
    }

    dim3 grid(NB / BT, NC);
    caps_route_kernel<<<grid, THREADS, smem_bytes>>>(x, W, out);
}

// round 10
// speedup vs baseline: 1.8108x; 1.8108x over previous
#include <cuda_runtime.h>
#include <cuda_fp16.h>

// CapsuleLayer dynamic routing — BT=2, full-line W loads, fp16 pair-packed
// P/E (fp32 compute), 512 threads, 2 CTAs/SM (64 regs, no spills).
// x: [256, 1152, 8] f32 ; W: [10, 1152, 8, 16] f32 ; out: [256, 10, 16] f32
#define NB 256
#define NC 10
#define NR 1152
#define IC 8
#define OC 16
#define THREADS 512
#define NWARP 16
#define BT 2
#define PSTR2 1154                // Pp row stride in half2 units (≡2 mod 32)
#define P2_UNITS (OC * PSTR2)
#define NUM_ITER 3

// SMEM 4B units: Pp | Ep[1156] | red2[16*33] | S2[32] | V[32] | red[64] | aux[8]
#define SMEM_FLOATS (P2_UNITS + 1156 + 16 * 33 + 32 + 32 + 64 + 8)

extern "C" __global__ void __launch_bounds__(THREADS, 2)
caps_route_kernel(const float* __restrict__ x,
                  const float* __restrict__ W,
                  float* __restrict__ out)
{
    extern __shared__ float sm[];
    __half2* Pp   = reinterpret_cast<__half2*>(sm);        // [oc][r], x=b0 y=b1
    __half2* Ep   = reinterpret_cast<__half2*>(sm + P2_UNITS);
    float*   red2 = sm + P2_UNITS + 1156;                  // [16][33]
    float*   S2   = red2 + 16 * 33;                        // [b*16+oc]
    float*   V    = S2 + 32;                               // 16B aligned
    float*   red  = V + 32;
    float*   aux  = red + 64;

    const int tid  = threadIdx.x;
    const int lane = tid & 31;
    const int wid  = tid >> 5;

    const int b0 = blockIdx.x * BT;
    const int c  = blockIdx.y;

    const float*  xb0 = x + (size_t)b0 * NR * IC;
    const float*  xb1 = xb0 + NR * IC;
    const float4* Wc4 = reinterpret_cast<const float4*>(
                            W + (size_t)c * NR * IC * OC);

    // ============ Phase 1: priors — full-line W loads, 1-level shfl merge ====
    // lane = rloc*8 + q ; q = qi*4 + sub. Warp owns 4 rows per chunk of 64;
    // 18 chunks. Post-merge both qi twins hold complete sums; twins split the
    // 4 packed half2 stores (banks distinct).
    {
        const int rloc  = lane >> 3;
        const int q     = lane & 7;
        const int qi    = q >> 2;
        const int sub   = q & 3;
        const int rbase = wid * 4 + rloc;

        float sA0 = 0.f, sA1 = 0.f, sA2 = 0.f, sA3 = 0.f;
        float sB0 = 0.f, sB1 = 0.f, sB2 = 0.f, sB3 = 0.f;

        #pragma unroll 3
        for (int it = 0; it < 18; ++it) {
            const int r = rbase + it * 64;
            const float4* wp = Wc4 + (size_t)r * 32 + q;
            const float4 w0 = wp[0];
            const float4 w1 = wp[8];
            const float4 w2 = wp[16];
            const float4 w3 = wp[24];
            const float4 xa0 = reinterpret_cast<const float4*>(xb0 + r * IC)[0];
            const float4 xa1 = reinterpret_cast<const float4*>(xb0 + r * IC)[1];
            const float4 xc0 = reinterpret_cast<const float4*>(xb1 + r * IC)[0];
            const float4 xc1 = reinterpret_cast<const float4*>(xb1 + r * IC)[1];

            const float xA0 = qi ? xa0.y : xa0.x;
            const float xA1 = qi ? xa0.w : xa0.z;
            const float xA2 = qi ? xa1.y : xa1.x;
            const float xA3 = qi ? xa1.w : xa1.z;
            const float xB0 = qi ? xc0.y : xc0.x;
            const float xB1 = qi ? xc0.w : xc0.z;
            const float xB2 = qi ? xc1.y : xc1.x;
            const float xB3 = qi ? xc1.w : xc1.z;

            float aA0, aA1, aA2, aA3, aB0, aB1, aB2, aB3;
            aA0 = xA0 * w0.x; aA1 = xA0 * w0.y; aA2 = xA0 * w0.z; aA3 = xA0 * w0.w;
            aB0 = xB0 * w0.x; aB1 = xB0 * w0.y; aB2 = xB0 * w0.z; aB3 = xB0 * w0.w;
            aA0 = fmaf(xA1, w1.x, aA0); aA1 = fmaf(xA1, w1.y, aA1);
            aA2 = fmaf(xA1, w1.z, aA2); aA3 = fmaf(xA1, w1.w, aA3);
            aB0 = fmaf(xB1, w1.x, aB0); aB1 = fmaf(xB1, w1.y, aB1);
            aB2 = fmaf(xB1, w1.z, aB2); aB3 = fmaf(xB1, w1.w, aB3);
            aA0 = fmaf(xA2, w2.x, aA0); aA1 = fmaf(xA2, w2.y, aA1);
            aA2 = fmaf(xA2, w2.z, aA2); aA3 = fmaf(xA2, w2.w, aA3);
            aB0 = fmaf(xB2, w2.x, aB0); aB1 = fmaf(xB2, w2.y, aB1);
            aB2 = fmaf(xB2, w2.z, aB2); aB3 = fmaf(xB2, w2.w, aB3);
            aA0 = fmaf(xA3, w3.x, aA0); aA1 = fmaf(xA3, w3.y, aA1);
            aA2 = fmaf(xA3, w3.z, aA2); aA3 = fmaf(xA3, w3.w, aA3);
            aB0 = fmaf(xB3, w3.x, aB0); aB1 = fmaf(xB3, w3.y, aB1);
            aB2 = fmaf(xB3, w3.z, aB2); aB3 = fmaf(xB3, w3.w, aB3);

            // merge i-parities — both twins end with complete sums
            aA0 += __shfl_xor_sync(0xFFFFFFFFu, aA0, 4);
            aA1 += __shfl_xor_sync(0xFFFFFFFFu, aA1, 4);
            aA2 += __shfl_xor_sync(0xFFFFFFFFu, aA2, 4);
            aA3 += __shfl_xor_sync(0xFFFFFFFFu, aA3, 4);
            aB0 += __shfl_xor_sync(0xFFFFFFFFu, aB0, 4);
            aB1 += __shfl_xor_sync(0xFFFFFFFFu, aB1, 4);
            aB2 += __shfl_xor_sync(0xFFFFFFFFu, aB2, 4);
            aB3 += __shfl_xor_sync(0xFFFFFFFFu, aB3, 4);

            // twins split the 4 packed stores
            const int ob = sub * 4 + qi * 2;
            const float p0a = qi ? aA2 : aA0;
            const float p0b = qi ? aB2 : aB0;
            const float p1a = qi ? aA3 : aA1;
            const float p1b = qi ? aB3 : aB1;
            Pp[(ob + 0) * PSTR2 + r] = __floats2half2_rn(p0a, p0b);
            Pp[(ob + 1) * PSTR2 + r] = __floats2half2_rn(p1a, p1b);

            sA0 += aA0; sA1 += aA1; sA2 += aA2; sA3 += aA3;
            sB0 += aB0; sB1 += aB1; sB2 += aB2; sB3 += aB3;
        }

        // reduce iter0 sums over rloc (lane bits 3,4); twins duplicate
        #pragma unroll
        for (int off = 8; off <= 16; off <<= 1) {
            sA0 += __shfl_xor_sync(0xFFFFFFFFu, sA0, off);
            sA1 += __shfl_xor_sync(0xFFFFFFFFu, sA1, off);
            sA2 += __shfl_xor_sync(0xFFFFFFFFu, sA2, off);
            sA3 += __shfl_xor_sync(0xFFFFFFFFu, sA3, off);
            sB0 += __shfl_xor_sync(0xFFFFFFFFu, sB0, off);
            sB1 += __shfl_xor_sync(0xFFFFFFFFu, sB1, off);
            sB2 += __shfl_xor_sync(0xFFFFFFFFu, sB2, off);
            sB3 += __shfl_xor_sync(0xFFFFFFFFu, sB3, off);
        }
        if (lane < 4) {           // rloc=0, qi=0, sub=lane
            float* row = red2 + wid * 33;
            row[lane * 4 + 0] = sA0;  row[lane * 4 + 1] = sA1;
            row[lane * 4 + 2] = sA2;  row[lane * 4 + 3] = sA3;
            row[16 + lane * 4 + 0] = sB0;  row[16 + lane * 4 + 1] = sB1;
            row[16 + lane * 4 + 2] = sB2;  row[16 + lane * 4 + 3] = sB3;
        }
    }
    __syncthreads();

    // ============ iter 0: squash from fused fp32 sums ========================
    const float inv_nr = 1.0f / (float)NR;
    if (wid == 0) {
        float s = 0.f;
        #pragma unroll
        for (int w2 = 0; w2 < NWARP; ++w2) s += red2[w2 * 33 + lane];
        float sv = s * inv_nr;
        float sq = sv * sv;
        #pragma unroll
        for (int off = 8; off > 0; off >>= 1)
            sq += __shfl_xor_sync(0xFFFFFFFFu, sq, off);   // within 16-half
        const float sc = sq / ((1.f + sq) * sqrtf(sq));
        V[lane] = sv * sc;
    }
    __syncthreads();

    // ============ Phase 2: routing iterations 1..2 ===========================
    // Thread owns rows: tid, tid+512, and tid+1024 when tid < 128.
    const int  ra   = tid;
    const int  rb   = tid + THREADS;
    const int  rc   = tid + 2 * THREADS;
    const bool hasc = (tid < NR - 2 * THREADS);   // tid < 128

    float La0 = 0.f, La1 = 0.f;
    float Lb0 = 0.f, Lb1 = 0.f;
    float Lc0 = 0.f, Lc1 = 0.f;

    for (int iter = 1; iter < NUM_ITER; ++iter) {
        // ---- delta logits (reads V of previous iteration; half2 P) ----
        {
            const float4* V4 = reinterpret_cast<const float4*>(V);
            float da0 = 0.f, da1 = 0.f, db0 = 0.f, db1 = 0.f;
            float dc0 = 0.f, dc1 = 0.f;
            #pragma unroll
            for (int o4 = 0; o4 < 4; ++o4) {
                const float4 v0 = V4[o4];
                const float4 v1 = V4[4 + o4];
                const float v0a[4] = {v0.x, v0.y, v0.z, v0.w};
                const float v1a[4] = {v1.x, v1.y, v1.z, v1.w};
                #pragma unroll
                for (int j = 0; j < 4; ++j) {
                    const int oc = o4 * 4 + j;
                    const float2 f = __half22float2(Pp[oc * PSTR2 + ra]);
                    da0 = fmaf(f.x, v0a[j], da0);
                    da1 = fmaf(f.y, v1a[j], da1);
                    const float2 g = __half22float2(Pp[oc * PSTR2 + rb]);
                    db0 = fmaf(g.x, v0a[j], db0);
                    db1 = fmaf(g.y, v1a[j], db1);
                    if (hasc) {
                        const float2 h = __half22float2(Pp[oc * PSTR2 + rc]);
                        dc0 = fmaf(h.x, v0a[j], dc0);
                        dc1 = fmaf(h.y, v1a[j], dc1);
                    }
                }
            }
            La0 += da0; La1 += da1;
            Lb0 += db0; Lb1 += db1;
            Lc0 += dc0; Lc1 += dc1;
        }

        // ---- softmax over r (both batches, fp32) ----
        {
            float m0 = fmaxf(La0, Lb0), m1 = fmaxf(La1, Lb1);
            if (hasc) { m0 = fmaxf(m0, Lc0); m1 = fmaxf(m1, Lc1); }
            #pragma unroll
            for (int off = 16; off > 0; off >>= 1) {
                m0 = fmaxf(m0, __shfl_xor_sync(0xFFFFFFFFu, m0, off));
                m1 = fmaxf(m1, __shfl_xor_sync(0xFFFFFFFFu, m1, off));
            }
            if (lane == 0) { red[wid] = m0; red[32 + wid] = m1; }
            __syncthreads();
            if (wid < 2) {
                float v = (lane < NWARP) ? red[wid * 32 + lane] : -1e30f;
                #pragma unroll
                for (int off = 8; off > 0; off >>= 1)
                    v = fmaxf(v, __shfl_xor_sync(0xFFFFFFFFu, v, off));
                if (lane == 0) aux[wid] = v;
            }
            __syncthreads();
            m0 = aux[0]; m1 = aux[1];

            float s0, s1;
            {
                const float ea0 = __expf(La0 - m0);
                const float ea1 = __expf(La1 - m1);
                const float eb0 = __expf(Lb0 - m0);
                const float eb1 = __expf(Lb1 - m1);
                Ep[ra] = __floats2half2_rn(ea0, ea1);
                Ep[rb] = __floats2half2_rn(eb0, eb1);
                s0 = ea0 + eb0; s1 = ea1 + eb1;
                if (hasc) {
                    const float ec0 = __expf(Lc0 - m0);
                    const float ec1 = __expf(Lc1 - m1);
                    Ep[rc] = __floats2half2_rn(ec0, ec1);
                    s0 += ec0; s1 += ec1;
                }
            }
            #pragma unroll
            for (int off = 16; off > 0; off >>= 1) {
                s0 += __shfl_xor_sync(0xFFFFFFFFu, s0, off);
                s1 += __shfl_xor_sync(0xFFFFFFFFu, s1, off);
            }
            if (lane == 0) { red[wid] = s0; red[32 + wid] = s1; }
            __syncthreads();
            if (wid < 2) {
                float v = (lane < NWARP) ? red[wid * 32 + lane] : 0.f;
                #pragma unroll
                for (int off = 8; off > 0; off >>= 1)
                    v += __shfl_xor_sync(0xFFFFFFFFu, v, off);
                if (lane == 0) aux[2 + wid] = 1.0f / v;
            }
            __syncthreads();   // Ep + aux visible
        }

        // ---- weighted sum: warp = oc; one half2 scan serves both batches ----
        {
            const __half2* pc = Pp + wid * PSTR2;
            float a0 = 0.f, a1 = 0.f;
            #pragma unroll 4
            for (int rr = lane; rr < NR; rr += 32) {
                const float2 e = __half22float2(Ep[rr]);
                const float2 p = __half22float2(pc[rr]);
                a0 = fmaf(e.x, p.x, a0);
                a1 = fmaf(e.y, p.y, a1);
            }
            #pragma unroll
            for (int off = 16; off > 0; off >>= 1) {
                a0 += __shfl_xor_sync(0xFFFFFFFFu, a0, off);
                a1 += __shfl_xor_sync(0xFFFFFFFFu, a1, off);
            }
            if (lane == 0) {
                S2[wid]      = a0;   // batch 0
                S2[16 + wid] = a1;   // batch 1
            }
        }
        __syncthreads();

        // ---- squash (warp 0; lanes 0-15 b0, 16-31 b1) ----
        if (wid == 0) {
            float sv = S2[lane] * aux[2 + (lane >> 4)];
            float sq = sv * sv;
            #pragma unroll
            for (int off = 8; off > 0; off >>= 1)
                sq += __shfl_xor_sync(0xFFFFFFFFu, sq, off);
            const float sc = sq / ((1.f + sq) * sqrtf(sq));
            V[lane] = sv * sc;
        }
        __syncthreads();
    }

    // ============ Phase 3: output ============================================
    if (tid < 2 * OC) {
        const int obb = tid >> 4;
        out[((size_t)(b0 + obb) * NC + c) * OC + (tid & 15)] = V[tid];
    }
}

extern "C" void kernel_launch(void* const* d_in, const int* in_sizes, int n_in,
                              void* d_out, int out_size)
{
    (void)in_sizes; (void)n_in; (void)out_size;
    const float* x = (const float*)d_in[0];
    const float* W = (const float*)d_in[1];
    float* out = (float*)d_out;

    static int smem_set = 0;
    const int smem_bytes = SMEM_FLOATS * sizeof(float);
    if (!smem_set) {
        cudaFuncSetAttribute(caps_route_kernel,
                             cudaFuncAttributeMaxDynamicSharedMemorySize,
                             smem_bytes);
        smem_set = 1;
    }

    dim3 grid(NB / BT, NC);
    caps_route_kernel<<<grid, THREADS, smem_bytes>>>(x, W, out);
}

// round 13
// speedup vs baseline: 2.0933x; 1.1560x over previous
#include <cuda_runtime.h>
#include <cuda_fp16.h>

// CapsuleLayer dynamic routing — BT=2, full-line W, fp16 pair-packed P/E with
// half2 merge; fp32 logit path (delta + WS + softmax). 512 thr, 2 CTAs/SM.
// x: [256, 1152, 8] f32 ; W: [10, 1152, 8, 16] f32 ; out: [256, 10, 16] f32
#define NB 256
#define NC 10
#define NR 1152
#define IC 8
#define OC 16
#define THREADS 512
#define NWARP 16
#define BT 2
#define PSTR2 1154                // Pp row stride in half2 units (≡2 mod 32)
#define P2_UNITS (OC * PSTR2)
#define NUM_ITER 3

// SMEM 4B units: Pp | Ep[1156] | red2[16*33] | S2[32] | V[32] | red[64] | aux[8]
#define SMEM_FLOATS (P2_UNITS + 1156 + 16 * 33 + 32 + 32 + 64 + 8)

__device__ __forceinline__ __half2 shfl_xor_h2(__half2 v, int off) {
    unsigned u = *reinterpret_cast<unsigned*>(&v);
    u = __shfl_xor_sync(0xFFFFFFFFu, u, off);
    return *reinterpret_cast<__half2*>(&u);
}

extern "C" __global__ void __launch_bounds__(THREADS, 2)
caps_route_kernel(const float* __restrict__ x,
                  const float* __restrict__ W,
                  float* __restrict__ out)
{
    extern __shared__ float sm[];
    __half2* Pp   = reinterpret_cast<__half2*>(sm);        // [oc][r], x=b0 y=b1
    __half2* Ep   = reinterpret_cast<__half2*>(sm + P2_UNITS);
    float*   red2 = sm + P2_UNITS + 1156;                  // [16][33]
    float*   S2   = red2 + 16 * 33;                        // [b*16+oc]
    float*   V    = S2 + 32;                               // fp32 outputs
    float*   red  = V + 32;
    float*   aux  = red + 64;

    const int tid  = threadIdx.x;
    const int lane = tid & 31;
    const int wid  = tid >> 5;

    const int b0 = blockIdx.x * BT;
    const int c  = blockIdx.y;

    const float*  xb0 = x + (size_t)b0 * NR * IC;
    const float*  xb1 = xb0 + NR * IC;
    const float4* Wc4 = reinterpret_cast<const float4*>(
                            W + (size_t)c * NR * IC * OC);

    // ============ Phase 1: priors — full-line W loads, half2 1-level merge ===
    // lane = rloc*8 + q ; q = qi*4 + sub. Warp owns 4 rows/chunk, 18 chunks.
    // Accumulators packed to half2(b0,b1) pre-merge; twins split packed stores.
    {
        const int rloc  = lane >> 3;
        const int q     = lane & 7;
        const int qi    = q >> 2;
        const int sub   = q & 3;
        const int rbase = wid * 4 + rloc;

        float sA0 = 0.f, sA1 = 0.f, sA2 = 0.f, sA3 = 0.f;  // pre-merge partials
        float sB0 = 0.f, sB1 = 0.f, sB2 = 0.f, sB3 = 0.f;

        #pragma unroll 3
        for (int it = 0; it < 18; ++it) {
            const int r = rbase + it * 64;
            const float4* wp = Wc4 + (size_t)r * 32 + q;
            const float4 w0 = wp[0];
            const float4 w1 = wp[8];
            const float4 w2 = wp[16];
            const float4 w3 = wp[24];
            // scalar qi-offset x loads (no selects)
            const float* xrA = xb0 + r * IC + qi;
            const float* xrB = xb1 + r * IC + qi;
            const float xA0 = xrA[0], xA1 = xrA[2], xA2 = xrA[4], xA3 = xrA[6];
            const float xB0 = xrB[0], xB1 = xrB[2], xB2 = xrB[4], xB3 = xrB[6];

            float aA0, aA1, aA2, aA3, aB0, aB1, aB2, aB3;
            aA0 = xA0 * w0.x; aA1 = xA0 * w0.y; aA2 = xA0 * w0.z; aA3 = xA0 * w0.w;
            aB0 = xB0 * w0.x; aB1 = xB0 * w0.y; aB2 = xB0 * w0.z; aB3 = xB0 * w0.w;
            aA0 = fmaf(xA1, w1.x, aA0); aA1 = fmaf(xA1, w1.y, aA1);
            aA2 = fmaf(xA1, w1.z, aA2); aA3 = fmaf(xA1, w1.w, aA3);
            aB0 = fmaf(xB1, w1.x, aB0); aB1 = fmaf(xB1, w1.y, aB1);
            aB2 = fmaf(xB1, w1.z, aB2); aB3 = fmaf(xB1, w1.w, aB3);
            aA0 = fmaf(xA2, w2.x, aA0); aA1 = fmaf(xA2, w2.y, aA1);
            aA2 = fmaf(xA2, w2.z, aA2); aA3 = fmaf(xA2, w2.w, aA3);
            aB0 = fmaf(xB2, w2.x, aB0); aB1 = fmaf(xB2, w2.y, aB1);
            aB2 = fmaf(xB2, w2.z, aB2); aB3 = fmaf(xB2, w2.w, aB3);
            aA0 = fmaf(xA3, w3.x, aA0); aA1 = fmaf(xA3, w3.y, aA1);
            aA2 = fmaf(xA3, w3.z, aA2); aA3 = fmaf(xA3, w3.w, aA3);
            aB0 = fmaf(xB3, w3.x, aB0); aB1 = fmaf(xB3, w3.y, aB1);
            aB2 = fmaf(xB3, w3.z, aB2); aB3 = fmaf(xB3, w3.w, aB3);

            // pack to half2(b0,b1), merge i-parities in fp16 (4 shfl + 4 hadd2)
            __half2 h0 = __floats2half2_rn(aA0, aB0);
            __half2 h1 = __floats2half2_rn(aA1, aB1);
            __half2 h2 = __floats2half2_rn(aA2, aB2);
            __half2 h3 = __floats2half2_rn(aA3, aB3);
            h0 = __hadd2(h0, shfl_xor_h2(h0, 4));
            h1 = __hadd2(h1, shfl_xor_h2(h1, 4));
            h2 = __hadd2(h2, shfl_xor_h2(h2, 4));
            h3 = __hadd2(h3, shfl_xor_h2(h3, 4));

            // twins split the stores: qi=0 -> h0,h1 ; qi=1 -> h2,h3
            const __half2 st0 = qi ? h2 : h0;
            const __half2 st1 = qi ? h3 : h1;
            const int ob = sub * 4 + qi * 2;
            Pp[(ob + 0) * PSTR2 + r] = st0;
            Pp[(ob + 1) * PSTR2 + r] = st1;

            // iter0 sums from fp32 pre-merge partials (exact path)
            sA0 += aA0; sA1 += aA1; sA2 += aA2; sA3 += aA3;
            sB0 += aB0; sB1 += aB1; sB2 += aB2; sB3 += aB3;
        }

        // reduce iter0 sums over qi (bit 2) and rloc (bits 3,4)
        #pragma unroll
        for (int off = 4; off <= 16; off <<= 1) {
            sA0 += __shfl_xor_sync(0xFFFFFFFFu, sA0, off);
            sA1 += __shfl_xor_sync(0xFFFFFFFFu, sA1, off);
            sA2 += __shfl_xor_sync(0xFFFFFFFFu, sA2, off);
            sA3 += __shfl_xor_sync(0xFFFFFFFFu, sA3, off);
            sB0 += __shfl_xor_sync(0xFFFFFFFFu, sB0, off);
            sB1 += __shfl_xor_sync(0xFFFFFFFFu, sB1, off);
            sB2 += __shfl_xor_sync(0xFFFFFFFFu, sB2, off);
            sB3 += __shfl_xor_sync(0xFFFFFFFFu, sB3, off);
        }
        if (lane < 4) {           // rloc=0, qi=0, sub=lane
            float* row = red2 + wid * 33;
            row[lane * 4 + 0] = sA0;  row[lane * 4 + 1] = sA1;
            row[lane * 4 + 2] = sA2;  row[lane * 4 + 3] = sA3;
            row[16 + lane * 4 + 0] = sB0;  row[16 + lane * 4 + 1] = sB1;
            row[16 + lane * 4 + 2] = sB2;  row[16 + lane * 4 + 3] = sB3;
        }
    }
    __syncthreads();

    // ============ iter 0: squash from fused fp32 sums ========================
    const float inv_nr = 1.0f / (float)NR;
    if (wid == 0) {
        float s = 0.f;
        #pragma unroll
        for (int w2 = 0; w2 < NWARP; ++w2) s += red2[w2 * 33 + lane];
        float sv = s * inv_nr;
        float sq = sv * sv;
        #pragma unroll
        for (int off = 8; off > 0; off >>= 1)
            sq += __shfl_xor_sync(0xFFFFFFFFu, sq, off);   // within 16-half
        const float sc = sq / ((1.f + sq) * sqrtf(sq));
        V[lane] = sv * sc;
    }
    __syncthreads();

    // ============ Phase 2: routing iterations 1..2 (fp32 logit path) =========
    const int  ra   = tid;
    const int  rb   = tid + THREADS;
    const int  rc   = tid + 2 * THREADS;
    const bool hasc = (tid < NR - 2 * THREADS);   // tid < 128

    float La0 = 0.f, La1 = 0.f;
    float Lb0 = 0.f, Lb1 = 0.f;
    float Lc0 = 0.f, Lc1 = 0.f;

    for (int iter = 1; iter < NUM_ITER; ++iter) {
        // ---- delta logits: fp32 unpack + FMA (precision-critical path) ----
        {
            const float4* V4 = reinterpret_cast<const float4*>(V);
            float da0 = 0.f, da1 = 0.f, db0 = 0.f, db1 = 0.f;
            float dc0 = 0.f, dc1 = 0.f;
            #pragma unroll
            for (int o4 = 0; o4 < 4; ++o4) {
                const float4 v0 = V4[o4];
                const float4 v1 = V4[4 + o4];
                const float v0a[4] = {v0.x, v0.y, v0.z, v0.w};
                const float v1a[4] = {v1.x, v1.y, v1.z, v1.w};
                #pragma unroll
                for (int j = 0; j < 4; ++j) {
                    const int oc = o4 * 4 + j;
                    const float2 f = __half22float2(Pp[oc * PSTR2 + ra]);
                    da0 = fmaf(f.x, v0a[j], da0);
                    da1 = fmaf(f.y, v1a[j], da1);
                    const float2 g = __half22float2(Pp[oc * PSTR2 + rb]);
                    db0 = fmaf(g.x, v0a[j], db0);
                    db1 = fmaf(g.y, v1a[j], db1);
                    if (hasc) {
                        const float2 h = __half22float2(Pp[oc * PSTR2 + rc]);
                        dc0 = fmaf(h.x, v0a[j], dc0);
                        dc1 = fmaf(h.y, v1a[j], dc1);
                    }
                }
            }
            La0 += da0; La1 += da1;
            Lb0 += db0; Lb1 += db1;
            Lc0 += dc0; Lc1 += dc1;
        }

        // ---- softmax over r (both batches, fp32) ----
        {
            float m0 = fmaxf(La0, Lb0), m1 = fmaxf(La1, Lb1);
            if (hasc) { m0 = fmaxf(m0, Lc0); m1 = fmaxf(m1, Lc1); }
            #pragma unroll
            for (int off = 16; off > 0; off >>= 1) {
                m0 = fmaxf(m0, __shfl_xor_sync(0xFFFFFFFFu, m0, off));
                m1 = fmaxf(m1, __shfl_xor_sync(0xFFFFFFFFu, m1, off));
            }
            if (lane == 0) { red[wid] = m0; red[32 + wid] = m1; }
            __syncthreads();
            if (wid < 2) {
                float v = (lane < NWARP) ? red[wid * 32 + lane] : -1e30f;
                #pragma unroll
                for (int off = 8; off > 0; off >>= 1)
                    v = fmaxf(v, __shfl_xor_sync(0xFFFFFFFFu, v, off));
                if (lane == 0) aux[wid] = v;
            }
            __syncthreads();
            m0 = aux[0]; m1 = aux[1];

            float s0, s1;
            {
                const float ea0 = __expf(La0 - m0);
                const float ea1 = __expf(La1 - m1);
                const float eb0 = __expf(Lb0 - m0);
                const float eb1 = __expf(Lb1 - m1);
                Ep[ra] = __floats2half2_rn(ea0, ea1);
                Ep[rb] = __floats2half2_rn(eb0, eb1);
                s0 = ea0 + eb0; s1 = ea1 + eb1;
                if (hasc) {
                    const float ec0 = __expf(Lc0 - m0);
                    const float ec1 = __expf(Lc1 - m1);
                    Ep[rc] = __floats2half2_rn(ec0, ec1);
                    s0 += ec0; s1 += ec1;
                }
            }
            #pragma unroll
            for (int off = 16; off > 0; off >>= 1) {
                s0 += __shfl_xor_sync(0xFFFFFFFFu, s0, off);
                s1 += __shfl_xor_sync(0xFFFFFFFFu, s1, off);
            }
            if (lane == 0) { red[wid] = s0; red[32 + wid] = s1; }
            __syncthreads();
            if (wid < 2) {
                float v = (lane < NWARP) ? red[wid * 32 + lane] : 0.f;
                #pragma unroll
                for (int off = 8; off > 0; off >>= 1)
                    v += __shfl_xor_sync(0xFFFFFFFFu, v, off);
                if (lane == 0) aux[2 + wid] = 1.0f / v;
            }
            __syncthreads();   // Ep + aux visible
        }

        // ---- weighted sum: warp = oc; fp32 convert + FMA ----
        {
            const __half2* pc = Pp + wid * PSTR2;
            float a0 = 0.f, a1 = 0.f;
            #pragma unroll 4
            for (int rr = lane; rr < NR; rr += 32) {
                const float2 e = __half22float2(Ep[rr]);
                const float2 p = __half22float2(pc[rr]);
                a0 = fmaf(e.x, p.x, a0);
                a1 = fmaf(e.y, p.y, a1);
            }
            #pragma unroll
            for (int off = 16; off > 0; off >>= 1) {
                a0 += __shfl_xor_sync(0xFFFFFFFFu, a0, off);
                a1 += __shfl_xor_sync(0xFFFFFFFFu, a1, off);
            }
            if (lane == 0) {
                S2[wid]      = a0;   // batch 0
                S2[16 + wid] = a1;   // batch 1
            }
        }
        __syncthreads();

        // ---- squash (warp 0; lanes 0-15 b0, 16-31 b1) ----
        if (wid == 0) {
            float sv = S2[lane] * aux[2 + (lane >> 4)];
            float sq = sv * sv;
            #pragma unroll
            for (int off = 8; off > 0; off >>= 1)
                sq += __shfl_xor_sync(0xFFFFFFFFu, sq, off);
            const float sc = sq / ((1.f + sq) * sqrtf(sq));
            V[lane] = sv * sc;
        }
        __syncthreads();
    }

    // ============ Phase 3: output ============================================
    if (tid < 2 * OC) {
        const int obb = tid >> 4;
        out[((size_t)(b0 + obb) * NC + c) * OC + (tid & 15)] = V[tid];
    }
}

extern "C" void kernel_launch(void* const* d_in, const int* in_sizes, int n_in,
                              void* d_out, int out_size)
{
    (void)in_sizes; (void)n_in; (void)out_size;
    const float* x = (const float*)d_in[0];
    const float* W = (const float*)d_in[1];
    float* out = (float*)d_out;

    static int smem_set = 0;
    const int smem_bytes = SMEM_FLOATS * sizeof(float);
    if (!smem_set) {
        cudaFuncSetAttribute(caps_route_kernel,
                             cudaFuncAttributeMaxDynamicSharedMemorySize,
                             smem_bytes);
        smem_set = 1;
    }

    dim3 grid(NB / BT, NC);
    caps_route_kernel<<<grid, THREADS, smem_bytes>>>(x, W, out);
}